// round 11
// baseline (speedup 1.0000x reference)
#include <cuda_runtime.h>
#include <cuda_fp16.h>
#include <cstdint>

#define BATCH    32768
#define IN_DIM   256
#define HID      512
#define OUT_DIM  128
#define NSTEPS   40
#define NSTAGE   (NSTEPS * 4)
#define DT       0.025f
#define HDT      0.0125f
#define DT6      (0.025f / 6.0f)
#define KP       1024            /* K' = 2 * HID (fp16 2-term split) */

// ---------------- static device scratch ----------------
__device__ __align__(128) __half g_S0h[(size_t)BATCH * HID];
__device__ __align__(128) __half g_S0l[(size_t)BATCH * HID];
__device__ __align__(128) __half g_S1h[(size_t)BATCH * HID];
__device__ __align__(128) __half g_S1l[(size_t)BATCH * HID];
__device__ __align__(128) __half g_S2h[(size_t)BATCH * HID];
__device__ __align__(128) __half g_S2l[(size_t)BATCH * HID];
__device__ __align__(128) __half g_S3h[(size_t)BATCH * HID];
__device__ __align__(128) __half g_S3l[(size_t)BATCH * HID];
__device__ __align__(128) __half g_Wbig[(size_t)HID * KP];   // [n][k']: Wf16 | Wf16
__device__ __align__(128) __half g_Ubig[(size_t)HID * KP];   // [n][k']: Uf16 | Uf16
__device__ __align__(128) float g_drive[(size_t)BATCH * HID];
__device__ __align__(128) float g_itau[HID];

__device__ __forceinline__ __half* Sh_ptr(int i) {
  switch (i) { case 0: return g_S0h; case 1: return g_S1h; case 2: return g_S2h; default: return g_S3h; }
}
__device__ __forceinline__ __half* Sl_ptr(int i) {
  switch (i) { case 0: return g_S0l; case 1: return g_S1l; case 2: return g_S2l; default: return g_S3l; }
}

// ---------------- helpers ----------------
__device__ __forceinline__ uint32_t smem_u32(const void* p) {
  uint32_t a;
  asm("{ .reg .u64 t; cvta.to.shared.u64 t, %1; cvt.u32.u64 %0, t; }" : "=r"(a) : "l"(p));
  return a;
}
__device__ __forceinline__ void cp16(uint32_t dst, const void* src) {
  asm volatile("cp.async.cg.shared.global [%0], [%1], 16;" :: "r"(dst), "l"(src) : "memory");
}
#define MBARRIER_INIT(a, c) \
  asm volatile("mbarrier.init.shared.b64 [%0], %1;" :: "r"(a), "r"((uint32_t)(c)) : "memory")
#define MBARRIER_ARRIVE(a) \
  asm volatile("mbarrier.arrive.shared.b64 _, [%0];" :: "r"(a) : "memory")
#define CPASYNC_MBAR_ARRIVE(a) \
  asm volatile("cp.async.mbarrier.arrive.noinc.shared::cta.b64 [%0];" :: "r"(a) : "memory")
#define MBAR_WAIT(a, ph) do {                                              \
  uint32_t _m = (a), _p = (uint32_t)(ph), _d;                              \
  asm volatile("{ .reg .pred p; mbarrier.try_wait.parity.acquire.cta.shared::cta.b64 p, [%1], %2; selp.b32 %0,1,0,p; }" \
               : "=r"(_d) : "r"(_m), "r"(_p) : "memory");                  \
  if (!_d) {                                                               \
    asm volatile("{ .reg .pred P1; WL%=: mbarrier.try_wait.parity.acquire.cta.shared::cta.b64 P1, [%0], %1, 0x989680; @P1 bra.uni WD%=; bra.uni WL%=; WD%=: }" \
                 :: "r"(_m), "r"(_p) : "memory");                          \
  }                                                                        \
} while (0)

#define LDSM4(r0, r1, r2, r3, a) \
  asm volatile("ldmatrix.sync.aligned.m8n8.x4.shared.b16 {%0,%1,%2,%3}, [%4];" \
               : "=r"(r0), "=r"(r1), "=r"(r2), "=r"(r3) : "r"(a))

#define MMA16816(d, a, b0, b1) \
  asm volatile("mma.sync.aligned.m16n8k16.row.col.f32.f16.f16.f32 " \
               "{%0,%1,%2,%3},{%4,%5,%6,%7},{%8,%9},{%0,%1,%2,%3};" \
               : "+f"((d)[0]), "+f"((d)[1]), "+f"((d)[2]), "+f"((d)[3]) \
               : "r"((a)[0]), "r"((a)[1]), "r"((a)[2]), "r"((a)[3]), "r"(b0), "r"(b1))

__device__ __forceinline__ float tanh_fast(float x) {
  float e = __expf(2.0f * x);
  return 1.0f - __fdividef(2.0f, e + 1.0f);
}

// ---------------- prep: W/U -> [f16 | f16] duplicated, itau ----------------
__global__ void k_prep(const float* __restrict__ W, const float* __restrict__ U,
                       const float* __restrict__ tau) {
  int idx = blockIdx.x * 256 + threadIdx.x;           // 2*512*1024 total
  const int HALF = HID * KP;
  int h = (idx >= HALF) ? 1 : 0;
  int j = idx - h * HALF;
  int n = j >> 10, k = j & (KP - 1);
  int kk = k & 511;
  const float* src = h ? U : W;
  __half* dst = h ? g_Ubig : g_Wbig;
  dst[j] = __float2half(src[n * 512 + kk]);
  if (idx < HID) g_itau[idx] = 1.0f / tau[idx];
}

// ---------------- fp32 microtile GEMM (k_in / k_head) ----------------
template <int K>
__device__ __forceinline__ void gemm_tile(const float* __restrict__ As,
                                          const float* __restrict__ Bg,
                                          int row0, int col0, float acc[4][16]) {
#pragma unroll
  for (int i = 0; i < 4; i++)
#pragma unroll
    for (int j = 0; j < 16; j++) acc[i][j] = 0.f;
#pragma unroll 1
  for (int k = 0; k < K; k += 4) {
    float4 a[4];
#pragma unroll
    for (int kk = 0; kk < 4; kk++)
      a[kk] = *reinterpret_cast<const float4*>(As + (k + kk) * 32 + row0);
    float4 bb[16];
#pragma unroll
    for (int j = 0; j < 16; j++)
      bb[j] = *reinterpret_cast<const float4*>(Bg + (size_t)(col0 + j) * K + k);
#pragma unroll
    for (int j = 0; j < 16; j++) {
      float bv[4] = {bb[j].x, bb[j].y, bb[j].z, bb[j].w};
#pragma unroll
      for (int kk = 0; kk < 4; kk++) {
        acc[0][j] = fmaf(a[kk].x, bv[kk], acc[0][j]);
        acc[1][j] = fmaf(a[kk].y, bv[kk], acc[1][j]);
        acc[2][j] = fmaf(a[kk].z, bv[kk], acc[2][j]);
        acc[3][j] = fmaf(a[kk].w, bv[kk], acc[3][j]);
      }
    }
  }
}

// u = x @ Wx^T + bx ; writes S0 (h0 = u) as fp16 hi/lo
__global__ void __launch_bounds__(256, 1)
k_in(const float* __restrict__ x, const float* __restrict__ Wx,
     const float* __restrict__ bx) {
  extern __shared__ float sm[];
  const int tid = threadIdx.x, b0 = blockIdx.x * 32;
  for (int idx = tid; idx < 32 * IN_DIM; idx += 256) {
    int m = idx >> 8, k = idx & 255;
    sm[k * 32 + m] = x[(size_t)(b0 + m) * IN_DIM + k];
  }
  __syncthreads();
  const int row0 = (tid & 7) * 4, col0 = (tid >> 3) * 16;
  float acc[4][16];
  gemm_tile<IN_DIM>(sm, Wx, row0, col0, acc);
#pragma unroll
  for (int j = 0; j < 16; j++) {
    float bxi = bx[col0 + j];
#pragma unroll
    for (int i = 0; i < 4; i++) {
      float v = acc[i][j] + bxi;
      size_t ix = (size_t)(b0 + row0 + i) * HID + col0 + j;
      __half hi = __float2half(v);
      g_S0h[ix] = hi;
      g_S0l[ix] = __float2half(v - __half2float(hi));
    }
  }
}

// out = h @ Wf^T + bf  (h = S0 hi+lo)
__global__ void __launch_bounds__(256, 1)
k_head(const float* __restrict__ Wf, const float* __restrict__ bf,
       float* __restrict__ out) {
  extern __shared__ float sm[];
  const int tid = threadIdx.x, b0 = blockIdx.x * 32;
  for (int idx = tid; idx < 32 * HID; idx += 256) {
    int m = idx >> 9, k = idx & 511;
    size_t ix = (size_t)(b0 + m) * HID + k;
    sm[k * 32 + m] = __half2float(g_S0h[ix]) + __half2float(g_S0l[ix]);
  }
  __syncthreads();
  const int row0 = (tid & 7) * 4, oc0 = (tid >> 3) * 4;
  float acc[4][4];
#pragma unroll
  for (int i = 0; i < 4; i++)
#pragma unroll
    for (int j = 0; j < 4; j++) acc[i][j] = 0.f;
#pragma unroll 1
  for (int k = 0; k < HID; k += 4) {
    float4 a[4];
#pragma unroll
    for (int kk = 0; kk < 4; kk++)
      a[kk] = *reinterpret_cast<const float4*>(sm + (k + kk) * 32 + row0);
#pragma unroll
    for (int j = 0; j < 4; j++) {
      float4 bb = *reinterpret_cast<const float4*>(Wf + (size_t)(oc0 + j) * HID + k);
      float bv[4] = {bb.x, bb.y, bb.z, bb.w};
#pragma unroll
      for (int kk = 0; kk < 4; kk++) {
        acc[0][j] = fmaf(a[kk].x, bv[kk], acc[0][j]);
        acc[1][j] = fmaf(a[kk].y, bv[kk], acc[1][j]);
        acc[2][j] = fmaf(a[kk].z, bv[kk], acc[2][j]);
        acc[3][j] = fmaf(a[kk].w, bv[kk], acc[3][j]);
      }
    }
  }
#pragma unroll
  for (int i = 0; i < 4; i++) {
    float4 o = make_float4(acc[i][0] + bf[oc0 + 0], acc[i][1] + bf[oc0 + 1],
                           acc[i][2] + bf[oc0 + 2], acc[i][3] + bf[oc0 + 3]);
    *reinterpret_cast<float4*>(out + (size_t)(b0 + row0 + i) * OUT_DIM + oc0) = o;
  }
}

// ---------------- pipeline constants ----------------
#define APITCH     144
#define A_BYTES    18432          /* 128*144 */
#define SSTRIDE    36864          /* A + B per stage slot */
#define NSTG       4
#define RING_BYTES (NSTG * SSTRIDE)
#define ST_SMEM    (RING_BYTES + 128)
#define N_CONS     512
#define N_PROD     64
#define NTHR       (N_CONS + N_PROD)
#define NCHUNK     16             /* K'=1024 / 64 */

// ---------------- drive kernel: drive = u @ U^T + b (one shot) -------------
__global__ void __launch_bounds__(NTHR, 1) k_drive(const float* __restrict__ bvec) {
  extern __shared__ __align__(128) char smem[];
  const uint32_t sb = smem_u32(smem);
  const uint32_t bar = sb + RING_BYTES;
  const int tid = threadIdx.x;
  const int b0 = blockIdx.x * 128;

  if (tid == 0) {
#pragma unroll
    for (int s = 0; s < NSTG; s++) {
      MBARRIER_INIT(bar + s * 16, N_PROD);
      MBARRIER_INIT(bar + s * 16 + 8, 16);
    }
  }
  __syncthreads();

  if (tid >= N_CONS) {
    const int t = tid - N_CONS;
    const int r0 = t >> 3, c = t & 7;
    int pst = 0, pph = 1;
#pragma unroll 1
    for (int nc = 0; nc < 4; ++nc) {
      const int n0 = nc * 128;
#pragma unroll 1
      for (int kc = 0; kc < NCHUNK; ++kc) {
        MBAR_WAIT(bar + pst * 16 + 8, pph);
        const __half* asrc = (kc >= 8) ? g_S0l : g_S0h;
        const int k0 = (kc & 7) << 6;
        const int kg = kc << 6;
        const uint32_t base = sb + pst * SSTRIDE;
        uint32_t ad = base + r0 * APITCH + c * 16;
        const __half* ap = asrc + (((size_t)(b0 + r0)) << 9) + k0 + c * 8;
        uint32_t bd = base + A_BYTES + r0 * APITCH + c * 16;
        const __half* bp = g_Ubig + ((size_t)(n0 + r0) << 10) + kg + c * 8;
#pragma unroll
        for (int j = 0; j < 16; j++) {
          cp16(ad, ap); cp16(bd, bp);
          ad += 8 * APITCH; ap += 8 * 512;
          bd += 8 * APITCH; bp += 8 * 1024;
        }
        CPASYNC_MBAR_ARRIVE(bar + pst * 16);
        if (++pst == NSTG) { pst = 0; pph ^= 1; }
      }
    }
  } else {
    const int lane = tid & 31, wid = tid >> 5;
    const int warp_m = wid & 3, warp_n = wid >> 2;
    const int lr = lane & 15, lc = lane >> 4;
    const uint32_t a_off = (warp_m * 32 + lr) * APITCH + lc * 16;
    const uint32_t b_off = A_BYTES + (warp_n * 32 + lr) * APITCH + lc * 16;
    int cst = 0, cph = 0;
#pragma unroll 1
    for (int nc = 0; nc < 4; ++nc) {
      const int n0 = nc * 128;
      float acc[2][4][4];
#pragma unroll
      for (int i = 0; i < 2; i++)
#pragma unroll
        for (int j = 0; j < 4; j++)
#pragma unroll
          for (int q = 0; q < 4; q++) acc[i][j][q] = 0.f;
#pragma unroll 1
      for (int kc = 0; kc < NCHUNK; ++kc) {
        MBAR_WAIT(bar + cst * 16, cph);
        const uint32_t ab = sb + cst * SSTRIDE + a_off;
        const uint32_t bb = sb + cst * SSTRIDE + b_off;
#pragma unroll
        for (int kk = 0; kk < 4; kk++) {
          uint32_t a[2][4], bfr[2][4];
          LDSM4(a[0][0], a[0][1], a[0][2], a[0][3], ab + kk * 32);
          LDSM4(a[1][0], a[1][1], a[1][2], a[1][3], ab + 16 * APITCH + kk * 32);
          LDSM4(bfr[0][0], bfr[0][1], bfr[0][2], bfr[0][3], bb + kk * 32);
          LDSM4(bfr[1][0], bfr[1][1], bfr[1][2], bfr[1][3], bb + 16 * APITCH + kk * 32);
#pragma unroll
          for (int fm = 0; fm < 2; fm++)
#pragma unroll
            for (int fn = 0; fn < 2; fn++) {
              MMA16816(acc[fm][2 * fn],     a[fm], bfr[fn][0], bfr[fn][2]);
              MMA16816(acc[fm][2 * fn + 1], a[fm], bfr[fn][1], bfr[fn][3]);
            }
        }
        if (lane == 0) MBARRIER_ARRIVE(bar + cst * 16 + 8);
        if (++cst == NSTG) { cst = 0; cph ^= 1; }
      }
      const int rq = lane >> 2, cq = (lane & 3) * 2;
#pragma unroll
      for (int fn = 0; fn < 4; fn++) {
        const int nn = n0 + warp_n * 32 + fn * 8 + cq;
        float2 bv = *reinterpret_cast<const float2*>(bvec + nn);
#pragma unroll
        for (int fm = 0; fm < 2; fm++)
#pragma unroll
          for (int half = 0; half < 2; half++) {
            const int r = b0 + warp_m * 32 + fm * 16 + rq + half * 8;
            const size_t ix = ((size_t)r << 9) + nn;
            *reinterpret_cast<float2*>(g_drive + ix) =
                make_float2(acc[fm][fn][half * 2] + bv.x,
                            acc[fm][fn][half * 2 + 1] + bv.y);
          }
      }
    }
  }
}

// ---------------- persistent fused ODE kernel: all 160 stages --------------
// Same ring/protocol as k_drive, plus a state_ready mbarrier (16 consumer-warp
// arrivals) gating the producer at each stage boundary (stage s+1 A reads
// depend on stage s epilogue writes; batch rows are CTA-private -> no
// inter-CTA sync needed anywhere).
__global__ void __launch_bounds__(NTHR, 1) k_ode() {
  extern __shared__ __align__(128) char smem[];
  const uint32_t sb = smem_u32(smem);
  const uint32_t bar = sb + RING_BYTES;      // full[s]@+16s, empty[s]@+16s+8
  const uint32_t sr_bar = bar + NSTG * 16;   // state_ready
  const int tid = threadIdx.x;
  const int b0 = blockIdx.x * 128;

  if (tid == 0) {
#pragma unroll
    for (int s = 0; s < NSTG; s++) {
      MBARRIER_INIT(bar + s * 16, N_PROD);
      MBARRIER_INIT(bar + s * 16 + 8, 16);
    }
    MBARRIER_INIT(sr_bar, 16);
  }
  __syncthreads();

  if (tid >= N_CONS) {
    // ---------------- producer: 2 warps, runs all 160 stages ----------------
    const int t = tid - N_CONS;
    const int r0 = t >> 3, c = t & 7;
    int pst = 0, pph = 1, srp = 0;
#pragma unroll 1
    for (int stage = 0; stage < NSTAGE; ++stage) {
      const int st = stage & 3;
      const __half* shi = Sh_ptr(st);
      const __half* slo = Sl_ptr(st);
      if (stage > 0) { MBAR_WAIT(sr_bar, srp); srp ^= 1; }  // state of this stage ready
#pragma unroll 1
      for (int nc = 0; nc < 4; ++nc) {
        const int n0 = nc * 128;
#pragma unroll 1
        for (int kc = 0; kc < NCHUNK; ++kc) {
          MBAR_WAIT(bar + pst * 16 + 8, pph);
          const __half* asrc = (kc >= 8) ? slo : shi;
          const int k0 = (kc & 7) << 6;
          const int kg = kc << 6;
          const uint32_t base = sb + pst * SSTRIDE;
          uint32_t ad = base + r0 * APITCH + c * 16;
          const __half* ap = asrc + (((size_t)(b0 + r0)) << 9) + k0 + c * 8;
          uint32_t bd = base + A_BYTES + r0 * APITCH + c * 16;
          const __half* bp = g_Wbig + ((size_t)(n0 + r0) << 10) + kg + c * 8;
#pragma unroll
          for (int j = 0; j < 16; j++) {
            cp16(ad, ap); cp16(bd, bp);
            ad += 8 * APITCH; ap += 8 * 512;
            bd += 8 * APITCH; bp += 8 * 1024;
          }
          CPASYNC_MBAR_ARRIVE(bar + pst * 16);
          if (++pst == NSTG) { pst = 0; pph ^= 1; }
        }
      }
    }
  } else {
    // ---------------- consumer: 16 warps ----------------
    const int lane = tid & 31, wid = tid >> 5;
    const int warp_m = wid & 3, warp_n = wid >> 2;
    const int lr = lane & 15, lc = lane >> 4;
    const uint32_t a_off = (warp_m * 32 + lr) * APITCH + lc * 16;
    const uint32_t b_off = A_BYTES + (warp_n * 32 + lr) * APITCH + lc * 16;
    int cst = 0, cph = 0;

#pragma unroll 1
    for (int stage = 0; stage < NSTAGE; ++stage) {
      const int st = stage & 3;
      const __half* shi = Sh_ptr(st);
      const __half* slo = Sl_ptr(st);
      __half* dsth = Sh_ptr((st + 1) & 3);
      __half* dstl = Sl_ptr((st + 1) & 3);

#pragma unroll 1
      for (int nc = 0; nc < 4; ++nc) {
        const int n0 = nc * 128;
        float acc[2][4][4];
#pragma unroll
        for (int i = 0; i < 2; i++)
#pragma unroll
          for (int j = 0; j < 4; j++)
#pragma unroll
            for (int q = 0; q < 4; q++) acc[i][j][q] = 0.f;

#pragma unroll 1
        for (int kc = 0; kc < NCHUNK; ++kc) {
          MBAR_WAIT(bar + cst * 16, cph);
          const uint32_t ab = sb + cst * SSTRIDE + a_off;
          const uint32_t bb = sb + cst * SSTRIDE + b_off;
#pragma unroll
          for (int kk = 0; kk < 4; kk++) {
            uint32_t a[2][4], bfr[2][4];
            LDSM4(a[0][0], a[0][1], a[0][2], a[0][3], ab + kk * 32);
            LDSM4(a[1][0], a[1][1], a[1][2], a[1][3], ab + 16 * APITCH + kk * 32);
            LDSM4(bfr[0][0], bfr[0][1], bfr[0][2], bfr[0][3], bb + kk * 32);
            LDSM4(bfr[1][0], bfr[1][1], bfr[1][2], bfr[1][3], bb + 16 * APITCH + kk * 32);
#pragma unroll
            for (int fm = 0; fm < 2; fm++)
#pragma unroll
              for (int fn = 0; fn < 2; fn++) {
                MMA16816(acc[fm][2 * fn],     a[fm], bfr[fn][0], bfr[fn][2]);
                MMA16816(acc[fm][2 * fn + 1], a[fm], bfr[fn][1], bfr[fn][3]);
              }
          }
          if (lane == 0) MBARRIER_ARRIVE(bar + cst * 16 + 8);
          if (++cst == NSTG) { cst = 0; cph ^= 1; }
        }

        // ---- fused RK4 epilogue on register fragments ----
        const int rq = lane >> 2, cq = (lane & 3) * 2;
#pragma unroll
        for (int fn = 0; fn < 4; fn++) {
          const int nn = n0 + warp_n * 32 + fn * 8 + cq;
#pragma unroll
          for (int fm = 0; fm < 2; fm++) {
#pragma unroll
            for (int half = 0; half < 2; half++) {
              const int r = b0 + warp_m * 32 + fm * 16 + rq + half * 8;
              const size_t ix = ((size_t)r << 9) + nn;
              const float c0 = acc[fm][fn][half * 2];
              const float c1 = acc[fm][fn][half * 2 + 1];
              const float2 it2 = *reinterpret_cast<const float2*>(g_itau + nn);
              float2 dr = *reinterpret_cast<const float2*>(g_drive + ix);
              float2 shf = __half22float2(*reinterpret_cast<const __half2*>(shi + ix));
              float2 slf = __half22float2(*reinterpret_cast<const __half2*>(slo + ix));
              float s0 = shf.x + slf.x;
              float s1 = shf.y + slf.y;
              float t0 = tanh_fast(c0 + dr.x);
              float t1 = tanh_fast(c1 + dr.y);
              float k0 = (t0 - s0) * it2.x;
              float k1 = (t1 - s1) * it2.y;
              float v0, v1;
              if (st == 0) {
                v0 = s0 + HDT * k0; v1 = s1 + HDT * k1;     // s2 = h + dt/2 k1
              } else {
                float2 hhf = __half22float2(*reinterpret_cast<const __half2*>(g_S0h + ix));
                float2 hlf = __half22float2(*reinterpret_cast<const __half2*>(g_S0l + ix));
                float h0 = hhf.x + hlf.x;
                float h1 = hhf.y + hlf.y;
                if (st == 1)      { v0 = h0 + HDT * k0; v1 = h1 + HDT * k1; }  // s3
                else if (st == 2) { v0 = h0 + DT * k0;  v1 = h1 + DT * k1;  }  // s4
                else {
                  float2 a2 = __half22float2(*reinterpret_cast<const __half2*>(g_S1h + ix));
                  float2 a2l = __half22float2(*reinterpret_cast<const __half2*>(g_S1l + ix));
                  float2 b2 = __half22float2(*reinterpret_cast<const __half2*>(g_S2h + ix));
                  float2 b2l = __half22float2(*reinterpret_cast<const __half2*>(g_S2l + ix));
                  float s20 = a2.x + a2l.x, s21 = a2.y + a2l.y;
                  float s30 = b2.x + b2l.x, s31 = b2.y + b2l.y;
                  v0 = h0 + (1.0f / 3.0f) * (s20 - h0) + (2.0f / 3.0f) * (s30 - h0)
                          + (1.0f / 3.0f) * (s0 - h0) + DT6 * k0;  // h_{n+1}
                  v1 = h1 + (1.0f / 3.0f) * (s21 - h1) + (2.0f / 3.0f) * (s31 - h1)
                          + (1.0f / 3.0f) * (s1 - h1) + DT6 * k1;
                }
              }
              __half hi0 = __float2half(v0);
              __half hi1 = __float2half(v1);
              __half2 oh; oh.x = hi0; oh.y = hi1;
              __half2 ol;
              ol.x = __float2half(v0 - __half2float(hi0));
              ol.y = __float2half(v1 - __half2float(hi1));
              *reinterpret_cast<__half2*>(dsth + ix) = oh;
              *reinterpret_cast<__half2*>(dstl + ix) = ol;
            }
          }
        }
      }
      // all 4 nc epilogues done: publish new state to producer
      __threadfence_block();
      if (lane == 0) MBARRIER_ARRIVE(sr_bar);
    }
  }
}

// ---------------- launcher ----------------
extern "C" void kernel_launch(void* const* d_in, const int* in_sizes, int n_in,
                              void* d_out, int out_size) {
  (void)in_sizes; (void)n_in; (void)out_size;
  const float* x    = (const float*)d_in[0];
  const float* Wx   = (const float*)d_in[1];
  const float* bx   = (const float*)d_in[2];
  const float* W    = (const float*)d_in[3];
  const float* U    = (const float*)d_in[4];
  const float* bvec = (const float*)d_in[5];
  const float* tau  = (const float*)d_in[6];
  const float* Wf   = (const float*)d_in[7];
  const float* bf   = (const float*)d_in[8];
  float* out = (float*)d_out;

  cudaFuncSetAttribute(k_drive, cudaFuncAttributeMaxDynamicSharedMemorySize, ST_SMEM);
  cudaFuncSetAttribute(k_ode,   cudaFuncAttributeMaxDynamicSharedMemorySize, ST_SMEM);
  cudaFuncSetAttribute(k_head,  cudaFuncAttributeMaxDynamicSharedMemorySize, 65536);
  cudaFuncSetAttribute(k_in,    cudaFuncAttributeMaxDynamicSharedMemorySize, 32768);

  k_prep<<<(2 * HID * KP) / 256, 256>>>(W, U, tau);
  k_in<<<BATCH / 32, 256, 32768>>>(x, Wx, bx);
  k_drive<<<BATCH / 128, NTHR, ST_SMEM>>>(bvec);
  k_ode<<<BATCH / 128, NTHR, ST_SMEM>>>();
  k_head<<<BATCH / 32, 256, 65536>>>(Wf, bf, out);
}

// round 13
// speedup vs baseline: 1.0053x; 1.0053x over previous
#include <cuda_runtime.h>
#include <cuda_fp16.h>
#include <cstdint>

#define BATCH    32768
#define IN_DIM   256
#define HID      512
#define OUT_DIM  128
#define NSTEPS   40
#define NSTAGE   (NSTEPS * 4)
#define DT       0.025f
#define HDT      0.0125f
#define DT6      (0.025f / 6.0f)
#define KP       1024            /* K' = 2 * HID (fp16 2-term split) */

// ---------------- static device scratch ----------------
__device__ __align__(128) __half g_S0h[(size_t)BATCH * HID];
__device__ __align__(128) __half g_S0l[(size_t)BATCH * HID];
__device__ __align__(128) __half g_S1h[(size_t)BATCH * HID];
__device__ __align__(128) __half g_S1l[(size_t)BATCH * HID];
__device__ __align__(128) __half g_S2h[(size_t)BATCH * HID];
__device__ __align__(128) __half g_S2l[(size_t)BATCH * HID];
__device__ __align__(128) __half g_S3h[(size_t)BATCH * HID];
__device__ __align__(128) __half g_S3l[(size_t)BATCH * HID];
__device__ __align__(128) __half g_Wbig[(size_t)HID * KP];   // [n][k']: Wf16 | Wf16
__device__ __align__(128) __half g_Ubig[(size_t)HID * KP];   // [n][k']: Uf16 | Uf16
__device__ __align__(128) float g_drive[(size_t)BATCH * HID];
__device__ __align__(128) float g_itau[HID];

__device__ __forceinline__ __half* Sh_ptr(int i) {
  switch (i) { case 0: return g_S0h; case 1: return g_S1h; case 2: return g_S2h; default: return g_S3h; }
}
__device__ __forceinline__ __half* Sl_ptr(int i) {
  switch (i) { case 0: return g_S0l; case 1: return g_S1l; case 2: return g_S2l; default: return g_S3l; }
}

// ---------------- helpers ----------------
__device__ __forceinline__ uint32_t smem_u32(const void* p) {
  uint32_t a;
  asm("{ .reg .u64 t; cvta.to.shared.u64 t, %1; cvt.u32.u64 %0, t; }" : "=r"(a) : "l"(p));
  return a;
}
__device__ __forceinline__ void cp16(uint32_t dst, const void* src) {
  asm volatile("cp.async.cg.shared.global [%0], [%1], 16;" :: "r"(dst), "l"(src) : "memory");
}
#define MBARRIER_INIT(a, c) \
  asm volatile("mbarrier.init.shared.b64 [%0], %1;" :: "r"(a), "r"((uint32_t)(c)) : "memory")
#define MBARRIER_ARRIVE(a) \
  asm volatile("mbarrier.arrive.shared.b64 _, [%0];" :: "r"(a) : "memory")
#define CPASYNC_MBAR_ARRIVE(a) \
  asm volatile("cp.async.mbarrier.arrive.noinc.shared::cta.b64 [%0];" :: "r"(a) : "memory")
#define MBAR_WAIT(a, ph) do {                                              \
  uint32_t _m = (a), _p = (uint32_t)(ph), _d;                              \
  asm volatile("{ .reg .pred p; mbarrier.try_wait.parity.acquire.cta.shared::cta.b64 p, [%1], %2; selp.b32 %0,1,0,p; }" \
               : "=r"(_d) : "r"(_m), "r"(_p) : "memory");                  \
  if (!_d) {                                                               \
    asm volatile("{ .reg .pred P1; WL%=: mbarrier.try_wait.parity.acquire.cta.shared::cta.b64 P1, [%0], %1, 0x989680; @P1 bra.uni WD%=; bra.uni WL%=; WD%=: }" \
                 :: "r"(_m), "r"(_p) : "memory");                          \
  }                                                                        \
} while (0)

#define LDSM4(r0, r1, r2, r3, a) \
  asm volatile("ldmatrix.sync.aligned.m8n8.x4.shared.b16 {%0,%1,%2,%3}, [%4];" \
               : "=r"(r0), "=r"(r1), "=r"(r2), "=r"(r3) : "r"(a))

#define MMA16816(d, a, b0, b1) \
  asm volatile("mma.sync.aligned.m16n8k16.row.col.f32.f16.f16.f32 " \
               "{%0,%1,%2,%3},{%4,%5,%6,%7},{%8,%9},{%0,%1,%2,%3};" \
               : "+f"((d)[0]), "+f"((d)[1]), "+f"((d)[2]), "+f"((d)[3]) \
               : "r"((a)[0]), "r"((a)[1]), "r"((a)[2]), "r"((a)[3]), "r"(b0), "r"(b1))

__device__ __forceinline__ float tanh_fast(float x) {
  float e = __expf(2.0f * x);
  return 1.0f - __fdividef(2.0f, e + 1.0f);
}

// ---------------- prep: W/U -> [f16 | f16] duplicated, itau ----------------
__global__ void k_prep(const float* __restrict__ W, const float* __restrict__ U,
                       const float* __restrict__ tau) {
  int idx = blockIdx.x * 256 + threadIdx.x;           // 2*512*1024 total
  const int HALF = HID * KP;
  int h = (idx >= HALF) ? 1 : 0;
  int j = idx - h * HALF;
  int n = j >> 10, k = j & (KP - 1);
  int kk = k & 511;
  const float* src = h ? U : W;
  __half* dst = h ? g_Ubig : g_Wbig;
  dst[j] = __float2half(src[n * 512 + kk]);
  if (idx < HID) g_itau[idx] = 1.0f / tau[idx];
}

// ---------------- fp32 microtile GEMM (k_in / k_head) ----------------
template <int K>
__device__ __forceinline__ void gemm_tile(const float* __restrict__ As,
                                          const float* __restrict__ Bg,
                                          int row0, int col0, float acc[4][16]) {
#pragma unroll
  for (int i = 0; i < 4; i++)
#pragma unroll
    for (int j = 0; j < 16; j++) acc[i][j] = 0.f;
#pragma unroll 1
  for (int k = 0; k < K; k += 4) {
    float4 a[4];
#pragma unroll
    for (int kk = 0; kk < 4; kk++)
      a[kk] = *reinterpret_cast<const float4*>(As + (k + kk) * 32 + row0);
    float4 bb[16];
#pragma unroll
    for (int j = 0; j < 16; j++)
      bb[j] = *reinterpret_cast<const float4*>(Bg + (size_t)(col0 + j) * K + k);
#pragma unroll
    for (int j = 0; j < 16; j++) {
      float bv[4] = {bb[j].x, bb[j].y, bb[j].z, bb[j].w};
#pragma unroll
      for (int kk = 0; kk < 4; kk++) {
        acc[0][j] = fmaf(a[kk].x, bv[kk], acc[0][j]);
        acc[1][j] = fmaf(a[kk].y, bv[kk], acc[1][j]);
        acc[2][j] = fmaf(a[kk].z, bv[kk], acc[2][j]);
        acc[3][j] = fmaf(a[kk].w, bv[kk], acc[3][j]);
      }
    }
  }
}

// u = x @ Wx^T + bx ; writes S0 (h0 = u) as fp16 hi/lo
__global__ void __launch_bounds__(256, 1)
k_in(const float* __restrict__ x, const float* __restrict__ Wx,
     const float* __restrict__ bx) {
  extern __shared__ float sm[];
  const int tid = threadIdx.x, b0 = blockIdx.x * 32;
  for (int idx = tid; idx < 32 * IN_DIM; idx += 256) {
    int m = idx >> 8, k = idx & 255;
    sm[k * 32 + m] = x[(size_t)(b0 + m) * IN_DIM + k];
  }
  __syncthreads();
  const int row0 = (tid & 7) * 4, col0 = (tid >> 3) * 16;
  float acc[4][16];
  gemm_tile<IN_DIM>(sm, Wx, row0, col0, acc);
#pragma unroll
  for (int j = 0; j < 16; j++) {
    float bxi = bx[col0 + j];
#pragma unroll
    for (int i = 0; i < 4; i++) {
      float v = acc[i][j] + bxi;
      size_t ix = (size_t)(b0 + row0 + i) * HID + col0 + j;
      __half hi = __float2half(v);
      g_S0h[ix] = hi;
      g_S0l[ix] = __float2half(v - __half2float(hi));
    }
  }
}

// out = h @ Wf^T + bf  (h = S0 hi+lo)
__global__ void __launch_bounds__(256, 1)
k_head(const float* __restrict__ Wf, const float* __restrict__ bf,
       float* __restrict__ out) {
  extern __shared__ float sm[];
  const int tid = threadIdx.x, b0 = blockIdx.x * 32;
  for (int idx = tid; idx < 32 * HID; idx += 256) {
    int m = idx >> 9, k = idx & 511;
    size_t ix = (size_t)(b0 + m) * HID + k;
    sm[k * 32 + m] = __half2float(g_S0h[ix]) + __half2float(g_S0l[ix]);
  }
  __syncthreads();
  const int row0 = (tid & 7) * 4, oc0 = (tid >> 3) * 4;
  float acc[4][4];
#pragma unroll
  for (int i = 0; i < 4; i++)
#pragma unroll
    for (int j = 0; j < 4; j++) acc[i][j] = 0.f;
#pragma unroll 1
  for (int k = 0; k < HID; k += 4) {
    float4 a[4];
#pragma unroll
    for (int kk = 0; kk < 4; kk++)
      a[kk] = *reinterpret_cast<const float4*>(sm + (k + kk) * 32 + row0);
#pragma unroll
    for (int j = 0; j < 4; j++) {
      float4 bb = *reinterpret_cast<const float4*>(Wf + (size_t)(oc0 + j) * HID + k);
      float bv[4] = {bb.x, bb.y, bb.z, bb.w};
#pragma unroll
      for (int kk = 0; kk < 4; kk++) {
        acc[0][j] = fmaf(a[kk].x, bv[kk], acc[0][j]);
        acc[1][j] = fmaf(a[kk].y, bv[kk], acc[1][j]);
        acc[2][j] = fmaf(a[kk].z, bv[kk], acc[2][j]);
        acc[3][j] = fmaf(a[kk].w, bv[kk], acc[3][j]);
      }
    }
  }
#pragma unroll
  for (int i = 0; i < 4; i++) {
    float4 o = make_float4(acc[i][0] + bf[oc0 + 0], acc[i][1] + bf[oc0 + 1],
                           acc[i][2] + bf[oc0 + 2], acc[i][3] + bf[oc0 + 3]);
    *reinterpret_cast<float4*>(out + (size_t)(b0 + row0 + i) * OUT_DIM + oc0) = o;
  }
}

// ---------------- pipeline constants ----------------
#define APITCH     144
#define A_BYTES    18432          /* 128*144 */
#define SSTRIDE    36864          /* A + B per stage slot */
#define NSTG       4
#define RING_BYTES (NSTG * SSTRIDE)
#define BAR_OFF    RING_BYTES                 /* full/empty barriers, 64 B */
#define CNT_OFF    (RING_BYTES + 64)          /* done[4] counters, 16 B */
#define ST_SMEM    (RING_BYTES + 128)
#define N_CONS     512
#define N_PROD     64
#define NTHR       (N_CONS + N_PROD)
#define NCHUNK     16             /* K'=1024 / 64 */

// ---------------- drive kernel: drive = u @ U^T + b (one shot) -------------
__global__ void __launch_bounds__(NTHR, 1) k_drive(const float* __restrict__ bvec) {
  extern __shared__ __align__(128) char smem[];
  const uint32_t sb = smem_u32(smem);
  const uint32_t bar = sb + BAR_OFF;
  const int tid = threadIdx.x;
  const int b0 = blockIdx.x * 128;

  if (tid == 0) {
#pragma unroll
    for (int s = 0; s < NSTG; s++) {
      MBARRIER_INIT(bar + s * 16, N_PROD);
      MBARRIER_INIT(bar + s * 16 + 8, 16);
    }
  }
  __syncthreads();

  if (tid >= N_CONS) {
    const int t = tid - N_CONS;
    const int r0 = t >> 3, c = t & 7;
    int pst = 0, pph = 1;
#pragma unroll 1
    for (int nc = 0; nc < 4; ++nc) {
      const int n0 = nc * 128;
#pragma unroll 1
      for (int kc = 0; kc < NCHUNK; ++kc) {
        MBAR_WAIT(bar + pst * 16 + 8, pph);
        const __half* asrc = (kc >= 8) ? g_S0l : g_S0h;
        const int k0 = (kc & 7) << 6;
        const int kg = kc << 6;
        const uint32_t base = sb + pst * SSTRIDE;
        uint32_t ad = base + r0 * APITCH + c * 16;
        const __half* ap = asrc + (((size_t)(b0 + r0)) << 9) + k0 + c * 8;
        uint32_t bd = base + A_BYTES + r0 * APITCH + c * 16;
        const __half* bp = g_Ubig + ((size_t)(n0 + r0) << 10) + kg + c * 8;
#pragma unroll
        for (int j = 0; j < 16; j++) {
          cp16(ad, ap); cp16(bd, bp);
          ad += 8 * APITCH; ap += 8 * 512;
          bd += 8 * APITCH; bp += 8 * 1024;
        }
        CPASYNC_MBAR_ARRIVE(bar + pst * 16);
        if (++pst == NSTG) { pst = 0; pph ^= 1; }
      }
    }
  } else {
    const int lane = tid & 31, wid = tid >> 5;
    const int warp_m = wid & 3, warp_n = wid >> 2;
    const int lr = lane & 15, lc = lane >> 4;
    const uint32_t a_off = (warp_m * 32 + lr) * APITCH + lc * 16;
    const uint32_t b_off = A_BYTES + (warp_n * 32 + lr) * APITCH + lc * 16;
    int cst = 0, cph = 0;
#pragma unroll 1
    for (int nc = 0; nc < 4; ++nc) {
      const int n0 = nc * 128;
      float acc[2][4][4];
#pragma unroll
      for (int i = 0; i < 2; i++)
#pragma unroll
        for (int j = 0; j < 4; j++)
#pragma unroll
          for (int q = 0; q < 4; q++) acc[i][j][q] = 0.f;
#pragma unroll 1
      for (int kc = 0; kc < NCHUNK; ++kc) {
        MBAR_WAIT(bar + cst * 16, cph);
        const uint32_t ab = sb + cst * SSTRIDE + a_off;
        const uint32_t bb = sb + cst * SSTRIDE + b_off;
#pragma unroll
        for (int kk = 0; kk < 4; kk++) {
          uint32_t a[2][4], bfr[2][4];
          LDSM4(a[0][0], a[0][1], a[0][2], a[0][3], ab + kk * 32);
          LDSM4(a[1][0], a[1][1], a[1][2], a[1][3], ab + 16 * APITCH + kk * 32);
          LDSM4(bfr[0][0], bfr[0][1], bfr[0][2], bfr[0][3], bb + kk * 32);
          LDSM4(bfr[1][0], bfr[1][1], bfr[1][2], bfr[1][3], bb + 16 * APITCH + kk * 32);
#pragma unroll
          for (int fm = 0; fm < 2; fm++)
#pragma unroll
            for (int fn = 0; fn < 2; fn++) {
              MMA16816(acc[fm][2 * fn],     a[fm], bfr[fn][0], bfr[fn][2]);
              MMA16816(acc[fm][2 * fn + 1], a[fm], bfr[fn][1], bfr[fn][3]);
            }
        }
        if (lane == 0) MBARRIER_ARRIVE(bar + cst * 16 + 8);
        if (++cst == NSTG) { cst = 0; cph ^= 1; }
      }
      const int rq = lane >> 2, cq = (lane & 3) * 2;
#pragma unroll
      for (int fn = 0; fn < 4; fn++) {
        const int nn = n0 + warp_n * 32 + fn * 8 + cq;
        float2 bv = *reinterpret_cast<const float2*>(bvec + nn);
#pragma unroll
        for (int fm = 0; fm < 2; fm++)
#pragma unroll
          for (int half = 0; half < 2; half++) {
            const int r = b0 + warp_m * 32 + fm * 16 + rq + half * 8;
            const size_t ix = ((size_t)r << 9) + nn;
            *reinterpret_cast<float2*>(g_drive + ix) =
                make_float2(acc[fm][fn][half * 2] + bv.x,
                            acc[fm][fn][half * 2 + 1] + bv.y);
          }
      }
    }
  }
}

// ---------------- persistent fused ODE kernel: all 160 stages --------------
// Fine-grained stage sync via MONOTONIC smem counters (hang-proof):
// consumer warps atomicAdd done[nc] after each column-quarter epilogue;
// producer spins until done[q] >= 16*stage before loading stage>=1 chunks
// of quarter q. Counters are monotonic -> no parity aliasing, no deadlock.
__global__ void __launch_bounds__(NTHR, 1) k_ode() {
  extern __shared__ __align__(128) char smem[];
  const uint32_t sb = smem_u32(smem);
  const uint32_t bar = sb + BAR_OFF;
  unsigned* done = reinterpret_cast<unsigned*>(smem + CNT_OFF);
  volatile unsigned* vdone = reinterpret_cast<volatile unsigned*>(smem + CNT_OFF);
  const int tid = threadIdx.x;
  const int b0 = blockIdx.x * 128;

  if (tid == 0) {
#pragma unroll
    for (int s = 0; s < NSTG; s++) {
      MBARRIER_INIT(bar + s * 16, N_PROD);
      MBARRIER_INIT(bar + s * 16 + 8, 16);
    }
#pragma unroll
    for (int q = 0; q < 4; q++) done[q] = 0u;
  }
  __syncthreads();

  if (tid >= N_CONS) {
    // ---------------- producer: 2 warps, runs all 160 stages ----------------
    const int t = tid - N_CONS;
    const int r0 = t >> 3, c = t & 7;
    int pst = 0, pph = 1;
#pragma unroll 1
    for (int stage = 0; stage < NSTAGE; ++stage) {
      const int st = stage & 3;
      const __half* shi = Sh_ptr(st);
      const __half* slo = Sl_ptr(st);
      const unsigned need = 16u * (unsigned)stage;
#pragma unroll 1
      for (int nc = 0; nc < 4; ++nc) {
        const int n0 = nc * 128;
#pragma unroll 1
        for (int kc = 0; kc < NCHUNK; ++kc) {
          if (stage > 0) {
            const int q = (kc & 7) >> 1;     // source column quarter
            while (vdone[q] < need) __nanosleep(64);
          }
          MBAR_WAIT(bar + pst * 16 + 8, pph);
          const __half* asrc = (kc >= 8) ? slo : shi;
          const int k0 = (kc & 7) << 6;
          const int kg = kc << 6;
          const uint32_t base = sb + pst * SSTRIDE;
          uint32_t ad = base + r0 * APITCH + c * 16;
          const __half* ap = asrc + (((size_t)(b0 + r0)) << 9) + k0 + c * 8;
          uint32_t bd = base + A_BYTES + r0 * APITCH + c * 16;
          const __half* bp = g_Wbig + ((size_t)(n0 + r0) << 10) + kg + c * 8;
#pragma unroll
          for (int j = 0; j < 16; j++) {
            cp16(ad, ap); cp16(bd, bp);
            ad += 8 * APITCH; ap += 8 * 512;
            bd += 8 * APITCH; bp += 8 * 1024;
          }
          CPASYNC_MBAR_ARRIVE(bar + pst * 16);
          if (++pst == NSTG) { pst = 0; pph ^= 1; }
        }
      }
    }
  } else {
    // ---------------- consumer: 16 warps ----------------
    const int lane = tid & 31, wid = tid >> 5;
    const int warp_m = wid & 3, warp_n = wid >> 2;
    const int lr = lane & 15, lc = lane >> 4;
    const uint32_t a_off = (warp_m * 32 + lr) * APITCH + lc * 16;
    const uint32_t b_off = A_BYTES + (warp_n * 32 + lr) * APITCH + lc * 16;
    int cst = 0, cph = 0;

#pragma unroll 1
    for (int stage = 0; stage < NSTAGE; ++stage) {
      const int st = stage & 3;
      const __half* shi = Sh_ptr(st);
      const __half* slo = Sl_ptr(st);
      __half* dsth = Sh_ptr((st + 1) & 3);
      __half* dstl = Sl_ptr((st + 1) & 3);

#pragma unroll 1
      for (int nc = 0; nc < 4; ++nc) {
        const int n0 = nc * 128;
        float acc[2][4][4];
#pragma unroll
        for (int i = 0; i < 2; i++)
#pragma unroll
          for (int j = 0; j < 4; j++)
#pragma unroll
            for (int q = 0; q < 4; q++) acc[i][j][q] = 0.f;

#pragma unroll 1
        for (int kc = 0; kc < NCHUNK; ++kc) {
          MBAR_WAIT(bar + cst * 16, cph);
          const uint32_t ab = sb + cst * SSTRIDE + a_off;
          const uint32_t bb = sb + cst * SSTRIDE + b_off;
#pragma unroll
          for (int kk = 0; kk < 4; kk++) {
            uint32_t a[2][4], bfr[2][4];
            LDSM4(a[0][0], a[0][1], a[0][2], a[0][3], ab + kk * 32);
            LDSM4(a[1][0], a[1][1], a[1][2], a[1][3], ab + 16 * APITCH + kk * 32);
            LDSM4(bfr[0][0], bfr[0][1], bfr[0][2], bfr[0][3], bb + kk * 32);
            LDSM4(bfr[1][0], bfr[1][1], bfr[1][2], bfr[1][3], bb + 16 * APITCH + kk * 32);
#pragma unroll
            for (int fm = 0; fm < 2; fm++)
#pragma unroll
              for (int fn = 0; fn < 2; fn++) {
                MMA16816(acc[fm][2 * fn],     a[fm], bfr[fn][0], bfr[fn][2]);
                MMA16816(acc[fm][2 * fn + 1], a[fm], bfr[fn][1], bfr[fn][3]);
              }
          }
          if (lane == 0) MBARRIER_ARRIVE(bar + cst * 16 + 8);
          if (++cst == NSTG) { cst = 0; cph ^= 1; }
        }

        // ---- fused RK4 epilogue on register fragments ----
        const int rq = lane >> 2, cq = (lane & 3) * 2;
#pragma unroll
        for (int fn = 0; fn < 4; fn++) {
          const int nn = n0 + warp_n * 32 + fn * 8 + cq;
#pragma unroll
          for (int fm = 0; fm < 2; fm++) {
#pragma unroll
            for (int half = 0; half < 2; half++) {
              const int r = b0 + warp_m * 32 + fm * 16 + rq + half * 8;
              const size_t ix = ((size_t)r << 9) + nn;
              const float c0 = acc[fm][fn][half * 2];
              const float c1 = acc[fm][fn][half * 2 + 1];
              const float2 it2 = *reinterpret_cast<const float2*>(g_itau + nn);
              float2 dr = *reinterpret_cast<const float2*>(g_drive + ix);
              float2 shf = __half22float2(*reinterpret_cast<const __half2*>(shi + ix));
              float2 slf = __half22float2(*reinterpret_cast<const __half2*>(slo + ix));
              float s0 = shf.x + slf.x;
              float s1 = shf.y + slf.y;
              float t0 = tanh_fast(c0 + dr.x);
              float t1 = tanh_fast(c1 + dr.y);
              float k0 = (t0 - s0) * it2.x;
              float k1 = (t1 - s1) * it2.y;
              float v0, v1;
              if (st == 0) {
                v0 = s0 + HDT * k0; v1 = s1 + HDT * k1;     // s2 = h + dt/2 k1
              } else {
                float2 hhf = __half22float2(*reinterpret_cast<const __half2*>(g_S0h + ix));
                float2 hlf = __half22float2(*reinterpret_cast<const __half2*>(g_S0l + ix));
                float h0 = hhf.x + hlf.x;
                float h1 = hhf.y + hlf.y;
                if (st == 1)      { v0 = h0 + HDT * k0; v1 = h1 + HDT * k1; }  // s3
                else if (st == 2) { v0 = h0 + DT * k0;  v1 = h1 + DT * k1;  }  // s4
                else {
                  float2 a2 = __half22float2(*reinterpret_cast<const __half2*>(g_S1h + ix));
                  float2 a2l = __half22float2(*reinterpret_cast<const __half2*>(g_S1l + ix));
                  float2 b2 = __half22float2(*reinterpret_cast<const __half2*>(g_S2h + ix));
                  float2 b2l = __half22float2(*reinterpret_cast<const __half2*>(g_S2l + ix));
                  float s20 = a2.x + a2l.x, s21 = a2.y + a2l.y;
                  float s30 = b2.x + b2l.x, s31 = b2.y + b2l.y;
                  v0 = h0 + (1.0f / 3.0f) * (s20 - h0) + (2.0f / 3.0f) * (s30 - h0)
                          + (1.0f / 3.0f) * (s0 - h0) + DT6 * k0;  // h_{n+1}
                  v1 = h1 + (1.0f / 3.0f) * (s21 - h1) + (2.0f / 3.0f) * (s31 - h1)
                          + (1.0f / 3.0f) * (s1 - h1) + DT6 * k1;
                }
              }
              __half hi0 = __float2half(v0);
              __half hi1 = __float2half(v1);
              __half2 oh; oh.x = hi0; oh.y = hi1;
              __half2 ol;
              ol.x = __float2half(v0 - __half2float(hi0));
              ol.y = __float2half(v1 - __half2float(hi1));
              *reinterpret_cast<__half2*>(dsth + ix) = oh;
              *reinterpret_cast<__half2*>(dstl + ix) = ol;
            }
          }
        }
        // publish this column-quarter of the new state to the producer
        __threadfence_block();
        if (lane == 0) atomicAdd(&done[nc], 1u);
      }
    }
  }
}

// ---------------- launcher ----------------
extern "C" void kernel_launch(void* const* d_in, const int* in_sizes, int n_in,
                              void* d_out, int out_size) {
  (void)in_sizes; (void)n_in; (void)out_size;
  const float* x    = (const float*)d_in[0];
  const float* Wx   = (const float*)d_in[1];
  const float* bx   = (const float*)d_in[2];
  const float* W    = (const float*)d_in[3];
  const float* U    = (const float*)d_in[4];
  const float* bvec = (const float*)d_in[5];
  const float* tau  = (const float*)d_in[6];
  const float* Wf   = (const float*)d_in[7];
  const float* bf   = (const float*)d_in[8];
  float* out = (float*)d_out;

  cudaFuncSetAttribute(k_drive, cudaFuncAttributeMaxDynamicSharedMemorySize, ST_SMEM);
  cudaFuncSetAttribute(k_ode,   cudaFuncAttributeMaxDynamicSharedMemorySize, ST_SMEM);
  cudaFuncSetAttribute(k_head,  cudaFuncAttributeMaxDynamicSharedMemorySize, 65536);
  cudaFuncSetAttribute(k_in,    cudaFuncAttributeMaxDynamicSharedMemorySize, 32768);

  k_prep<<<(2 * HID * KP) / 256, 256>>>(W, U, tau);
  k_in<<<BATCH / 32, 256, 32768>>>(x, Wx, bx);
  k_drive<<<BATCH / 128, NTHR, ST_SMEM>>>(bvec);
  k_ode<<<BATCH / 128, NTHR, ST_SMEM>>>();
  k_head<<<BATCH / 32, 256, 65536>>>(Wf, bf, out);
}

// round 14
// speedup vs baseline: 1.4224x; 1.4149x over previous
#include <cuda_runtime.h>
#include <cuda_fp16.h>
#include <cstdint>

#define BATCH    32768
#define IN_DIM   256
#define HID      512
#define OUT_DIM  128
#define NSTEPS   40
#define DT       0.025f
#define HDT      0.0125f
#define DT3      (0.025f / 3.0f)
#define DT6      (0.025f / 6.0f)

// ---------------- static device scratch ----------------
__device__ __align__(128) __half g_Hh[(size_t)BATCH * HID];    // h hi (also k1 GEMM A)
__device__ __align__(128) __half g_Hl[(size_t)BATCH * HID];    // h lo
__device__ __align__(128) __half g_A1[(size_t)BATCH * HID];    // s2 (fp16 single)
__device__ __align__(128) __half g_A2[(size_t)BATCH * HID];    // s3
__device__ __align__(128) __half g_A3[(size_t)BATCH * HID];    // s4
__device__ __align__(128) float  g_Acc[(size_t)BATCH * HID];   // fp32 RK4 accumulator
__device__ __align__(128) __half g_W16[(size_t)HID * HID];     // [n][k] W fp16
__device__ __align__(128) __half g_Ubig[(size_t)HID * 1024];   // [n][k']: Uf16 | Uf16
__device__ __align__(128) float  g_drive[(size_t)BATCH * HID];
__device__ __align__(128) float  g_itau[HID];

// ---------------- helpers ----------------
__device__ __forceinline__ uint32_t smem_u32(const void* p) {
  uint32_t a;
  asm("{ .reg .u64 t; cvta.to.shared.u64 t, %1; cvt.u32.u64 %0, t; }" : "=r"(a) : "l"(p));
  return a;
}
__device__ __forceinline__ void cp16(uint32_t dst, const void* src) {
  asm volatile("cp.async.cg.shared.global [%0], [%1], 16;" :: "r"(dst), "l"(src) : "memory");
}
#define MBARRIER_INIT(a, c) \
  asm volatile("mbarrier.init.shared.b64 [%0], %1;" :: "r"(a), "r"((uint32_t)(c)) : "memory")
#define MBARRIER_ARRIVE(a) \
  asm volatile("mbarrier.arrive.shared.b64 _, [%0];" :: "r"(a) : "memory")
#define CPASYNC_MBAR_ARRIVE(a) \
  asm volatile("cp.async.mbarrier.arrive.noinc.shared::cta.b64 [%0];" :: "r"(a) : "memory")
#define MBAR_WAIT(a, ph) do {                                              \
  uint32_t _m = (a), _p = (uint32_t)(ph), _d;                              \
  asm volatile("{ .reg .pred p; mbarrier.try_wait.parity.acquire.cta.shared::cta.b64 p, [%1], %2; selp.b32 %0,1,0,p; }" \
               : "=r"(_d) : "r"(_m), "r"(_p) : "memory");                  \
  if (!_d) {                                                               \
    asm volatile("{ .reg .pred P1; WL%=: mbarrier.try_wait.parity.acquire.cta.shared::cta.b64 P1, [%0], %1, 0x989680; @P1 bra.uni WD%=; bra.uni WL%=; WD%=: }" \
                 :: "r"(_m), "r"(_p) : "memory");                          \
  }                                                                        \
} while (0)

#define LDSM4(r0, r1, r2, r3, a) \
  asm volatile("ldmatrix.sync.aligned.m8n8.x4.shared.b16 {%0,%1,%2,%3}, [%4];" \
               : "=r"(r0), "=r"(r1), "=r"(r2), "=r"(r3) : "r"(a))

#define MMA16816(d, a, b0, b1) \
  asm volatile("mma.sync.aligned.m16n8k16.row.col.f32.f16.f16.f32 " \
               "{%0,%1,%2,%3},{%4,%5,%6,%7},{%8,%9},{%0,%1,%2,%3};" \
               : "+f"((d)[0]), "+f"((d)[1]), "+f"((d)[2]), "+f"((d)[3]) \
               : "r"((a)[0]), "r"((a)[1]), "r"((a)[2]), "r"((a)[3]), "r"(b0), "r"(b1))

__device__ __forceinline__ float tanh_fast(float x) {
  float e = __expf(2.0f * x);
  return 1.0f - __fdividef(2.0f, e + 1.0f);
}

// ---------------- prep: W -> f16, U -> [f16|f16], itau ----------------
__global__ void k_prep(const float* __restrict__ W, const float* __restrict__ U,
                       const float* __restrict__ tau) {
  int idx = blockIdx.x * 256 + threadIdx.x;   // 512*512 + 512*1024 = 786432
  const int WSZ = HID * HID;
  if (idx < WSZ) {
    g_W16[idx] = __float2half(W[idx]);
  } else {
    int j = idx - WSZ;                        // over 512*1024
    int n = j >> 10, k = j & 1023;
    g_Ubig[j] = __float2half(U[n * 512 + (k & 511)]);
  }
  if (idx < HID) g_itau[idx] = 1.0f / tau[idx];
}

// ---------------- fp32 microtile GEMM (k_in / k_head) ----------------
template <int K>
__device__ __forceinline__ void gemm_tile(const float* __restrict__ As,
                                          const float* __restrict__ Bg,
                                          int row0, int col0, float acc[4][16]) {
#pragma unroll
  for (int i = 0; i < 4; i++)
#pragma unroll
    for (int j = 0; j < 16; j++) acc[i][j] = 0.f;
#pragma unroll 1
  for (int k = 0; k < K; k += 4) {
    float4 a[4];
#pragma unroll
    for (int kk = 0; kk < 4; kk++)
      a[kk] = *reinterpret_cast<const float4*>(As + (k + kk) * 32 + row0);
    float4 bb[16];
#pragma unroll
    for (int j = 0; j < 16; j++)
      bb[j] = *reinterpret_cast<const float4*>(Bg + (size_t)(col0 + j) * K + k);
#pragma unroll
    for (int j = 0; j < 16; j++) {
      float bv[4] = {bb[j].x, bb[j].y, bb[j].z, bb[j].w};
#pragma unroll
      for (int kk = 0; kk < 4; kk++) {
        acc[0][j] = fmaf(a[kk].x, bv[kk], acc[0][j]);
        acc[1][j] = fmaf(a[kk].y, bv[kk], acc[1][j]);
        acc[2][j] = fmaf(a[kk].z, bv[kk], acc[2][j]);
        acc[3][j] = fmaf(a[kk].w, bv[kk], acc[3][j]);
      }
    }
  }
}

// u = x @ Wx^T + bx ; writes h0 = u as fp16 hi/lo
__global__ void __launch_bounds__(256, 1)
k_in(const float* __restrict__ x, const float* __restrict__ Wx,
     const float* __restrict__ bx) {
  extern __shared__ float sm[];
  const int tid = threadIdx.x, b0 = blockIdx.x * 32;
  for (int idx = tid; idx < 32 * IN_DIM; idx += 256) {
    int m = idx >> 8, k = idx & 255;
    sm[k * 32 + m] = x[(size_t)(b0 + m) * IN_DIM + k];
  }
  __syncthreads();
  const int row0 = (tid & 7) * 4, col0 = (tid >> 3) * 16;
  float acc[4][16];
  gemm_tile<IN_DIM>(sm, Wx, row0, col0, acc);
#pragma unroll
  for (int j = 0; j < 16; j++) {
    float bxi = bx[col0 + j];
#pragma unroll
    for (int i = 0; i < 4; i++) {
      float v = acc[i][j] + bxi;
      size_t ix = (size_t)(b0 + row0 + i) * HID + col0 + j;
      __half hi = __float2half(v);
      g_Hh[ix] = hi;
      g_Hl[ix] = __float2half(v - __half2float(hi));
    }
  }
}

// out = h @ Wf^T + bf  (h = Hh+Hl)
__global__ void __launch_bounds__(256, 1)
k_head(const float* __restrict__ Wf, const float* __restrict__ bf,
       float* __restrict__ out) {
  extern __shared__ float sm[];
  const int tid = threadIdx.x, b0 = blockIdx.x * 32;
  for (int idx = tid; idx < 32 * HID; idx += 256) {
    int m = idx >> 9, k = idx & 511;
    size_t ix = (size_t)(b0 + m) * HID + k;
    sm[k * 32 + m] = __half2float(g_Hh[ix]) + __half2float(g_Hl[ix]);
  }
  __syncthreads();
  const int row0 = (tid & 7) * 4, oc0 = (tid >> 3) * 4;
  float acc[4][4];
#pragma unroll
  for (int i = 0; i < 4; i++)
#pragma unroll
    for (int j = 0; j < 4; j++) acc[i][j] = 0.f;
#pragma unroll 1
  for (int k = 0; k < HID; k += 4) {
    float4 a[4];
#pragma unroll
    for (int kk = 0; kk < 4; kk++)
      a[kk] = *reinterpret_cast<const float4*>(sm + (k + kk) * 32 + row0);
#pragma unroll
    for (int j = 0; j < 4; j++) {
      float4 bb = *reinterpret_cast<const float4*>(Wf + (size_t)(oc0 + j) * HID + k);
      float bv[4] = {bb.x, bb.y, bb.z, bb.w};
#pragma unroll
      for (int kk = 0; kk < 4; kk++) {
        acc[0][j] = fmaf(a[kk].x, bv[kk], acc[0][j]);
        acc[1][j] = fmaf(a[kk].y, bv[kk], acc[1][j]);
        acc[2][j] = fmaf(a[kk].z, bv[kk], acc[2][j]);
        acc[3][j] = fmaf(a[kk].w, bv[kk], acc[3][j]);
      }
    }
  }
#pragma unroll
  for (int i = 0; i < 4; i++) {
    float4 o = make_float4(acc[i][0] + bf[oc0 + 0], acc[i][1] + bf[oc0 + 1],
                           acc[i][2] + bf[oc0 + 2], acc[i][3] + bf[oc0 + 3]);
    *reinterpret_cast<float4*>(out + (size_t)(b0 + row0 + i) * OUT_DIM + oc0) = o;
  }
}

// ---------------- warp-specialized HMMA GEMM kernel ----------------
// MODE 0..3: RK4 stage st=MODE, A = single fp16 stage array, K'=512 (8 chunks).
// MODE 4: drive = u @ U^T + b, A = Hh|Hl, K'=1024 (16 chunks).
// 576 threads: 16 consumer warps (4M x 4N, 32x32 tiles) + 2 producer warps,
// 4-slot cp.async ring with full/empty mbarriers.
#define APITCH     144
#define A_BYTES    18432          /* 128*144 */
#define SSTRIDE    36864          /* A + B per slot */
#define NSTG       4
#define RING_BYTES (NSTG * SSTRIDE)
#define ST_SMEM    (RING_BYTES + 128)
#define N_CONS     512
#define N_PROD     64
#define NTHR       (N_CONS + N_PROD)

template <int MODE>
__global__ void __launch_bounds__(NTHR, 1) k_gemm(const float* __restrict__ bvec) {
  constexpr int NCH = (MODE == 4) ? 16 : 8;
  constexpr int BSTRIDE = (MODE == 4) ? 1024 : 512;
  extern __shared__ __align__(128) char smem[];
  const uint32_t sb = smem_u32(smem);
  const uint32_t bar = sb + RING_BYTES;
  const int tid = threadIdx.x;
  const int b0 = blockIdx.x * 128;

  const __half* Amat = (MODE == 0 || MODE == 4) ? g_Hh
                     : (MODE == 1) ? g_A1 : (MODE == 2) ? g_A2 : g_A3;
  const __half* Bmat = (MODE == 4) ? g_Ubig : g_W16;

  if (tid == 0) {
#pragma unroll
    for (int s = 0; s < NSTG; s++) {
      MBARRIER_INIT(bar + s * 16, N_PROD);
      MBARRIER_INIT(bar + s * 16 + 8, 16);
    }
  }
  __syncthreads();

  if (tid >= N_CONS) {
    // ---------------- producer: 2 warps ----------------
    const int t = tid - N_CONS;
    const int r0 = t >> 3, c = t & 7;
    int pst = 0, pph = 1;
#pragma unroll 1
    for (int nc = 0; nc < 4; ++nc) {
      const int n0 = nc * 128;
#pragma unroll 1
      for (int kc = 0; kc < NCH; ++kc) {
        MBAR_WAIT(bar + pst * 16 + 8, pph);
        const __half* asrc = (MODE == 4 && kc >= 8) ? g_Hl : Amat;
        const int k0 = (kc & 7) << 6;
        const int kg = kc << 6;
        const uint32_t base = sb + pst * SSTRIDE;
        uint32_t ad = base + r0 * APITCH + c * 16;
        const __half* ap = asrc + (((size_t)(b0 + r0)) << 9) + k0 + c * 8;
        uint32_t bd = base + A_BYTES + r0 * APITCH + c * 16;
        const __half* bp = Bmat + (size_t)(n0 + r0) * BSTRIDE + kg + c * 8;
#pragma unroll
        for (int j = 0; j < 16; j++) {       // 128 rows of A and B
          cp16(ad, ap); cp16(bd, bp);
          ad += 8 * APITCH; ap += 8 * 512;
          bd += 8 * APITCH; bp += 8 * BSTRIDE;
        }
        CPASYNC_MBAR_ARRIVE(bar + pst * 16);
        if (++pst == NSTG) { pst = 0; pph ^= 1; }
      }
    }
  } else {
    // ---------------- consumer: 16 warps ----------------
    const int lane = tid & 31, wid = tid >> 5;
    const int warp_m = wid & 3, warp_n = wid >> 2;
    const int lr = lane & 15, lc = lane >> 4;
    const uint32_t a_off = (warp_m * 32 + lr) * APITCH + lc * 16;
    const uint32_t b_off = A_BYTES + (warp_n * 32 + lr) * APITCH + lc * 16;
    int cst = 0, cph = 0;

#pragma unroll 1
    for (int nc = 0; nc < 4; ++nc) {
      const int n0 = nc * 128;
      float acc[2][4][4];
#pragma unroll
      for (int i = 0; i < 2; i++)
#pragma unroll
        for (int j = 0; j < 4; j++)
#pragma unroll
          for (int q = 0; q < 4; q++) acc[i][j][q] = 0.f;

#pragma unroll 1
      for (int kc = 0; kc < NCH; ++kc) {
        MBAR_WAIT(bar + cst * 16, cph);
        const uint32_t ab = sb + cst * SSTRIDE + a_off;
        const uint32_t bb = sb + cst * SSTRIDE + b_off;
#pragma unroll
        for (int kk = 0; kk < 4; kk++) {
          uint32_t a[2][4], bfr[2][4];
          LDSM4(a[0][0], a[0][1], a[0][2], a[0][3], ab + kk * 32);
          LDSM4(a[1][0], a[1][1], a[1][2], a[1][3], ab + 16 * APITCH + kk * 32);
          LDSM4(bfr[0][0], bfr[0][1], bfr[0][2], bfr[0][3], bb + kk * 32);
          LDSM4(bfr[1][0], bfr[1][1], bfr[1][2], bfr[1][3], bb + 16 * APITCH + kk * 32);
#pragma unroll
          for (int fm = 0; fm < 2; fm++)
#pragma unroll
            for (int fn = 0; fn < 2; fn++) {
              MMA16816(acc[fm][2 * fn],     a[fm], bfr[fn][0], bfr[fn][2]);
              MMA16816(acc[fm][2 * fn + 1], a[fm], bfr[fn][1], bfr[fn][3]);
            }
        }
        if (lane == 0) MBARRIER_ARRIVE(bar + cst * 16 + 8);
        if (++cst == NSTG) { cst = 0; cph ^= 1; }
      }

      // ---- fused RK4 epilogue on register fragments ----
      const int rq = lane >> 2, cq = (lane & 3) * 2;
#pragma unroll
      for (int fn = 0; fn < 4; fn++) {
        const int nn = n0 + warp_n * 32 + fn * 8 + cq;
#pragma unroll
        for (int fm = 0; fm < 2; fm++) {
#pragma unroll
          for (int half = 0; half < 2; half++) {
            const int r = b0 + warp_m * 32 + fm * 16 + rq + half * 8;
            const size_t ix = ((size_t)r << 9) + nn;
            const float c0 = acc[fm][fn][half * 2];
            const float c1 = acc[fm][fn][half * 2 + 1];
            if (MODE == 4) {
              float2 bv = *reinterpret_cast<const float2*>(bvec + nn);
              *reinterpret_cast<float2*>(g_drive + ix) =
                  make_float2(c0 + bv.x, c1 + bv.y);
            } else {
              const float2 it2 = *reinterpret_cast<const float2*>(g_itau + nn);
              float2 dr = *reinterpret_cast<const float2*>(g_drive + ix);
              float t0 = tanh_fast(c0 + dr.x);
              float t1 = tanh_fast(c1 + dr.y);
              if (MODE == 0) {
                float2 hh = __half22float2(*reinterpret_cast<const __half2*>(g_Hh + ix));
                float2 hl = __half22float2(*reinterpret_cast<const __half2*>(g_Hl + ix));
                float h0 = hh.x + hl.x, h1 = hh.y + hl.y;
                float k0 = (t0 - h0) * it2.x;
                float k1 = (t1 - h1) * it2.y;
                *reinterpret_cast<float2*>(g_Acc + ix) =
                    make_float2(h0 + DT6 * k0, h1 + DT6 * k1);
                __half2 s2;
                s2.x = __float2half(h0 + HDT * k0);
                s2.y = __float2half(h1 + HDT * k1);
                *reinterpret_cast<__half2*>(g_A1 + ix) = s2;
              } else if (MODE == 1 || MODE == 2) {
                const __half* Sarr = (MODE == 1) ? g_A1 : g_A2;
                float2 sv = __half22float2(*reinterpret_cast<const __half2*>(Sarr + ix));
                float k0 = (t0 - sv.x) * it2.x;
                float k1 = (t1 - sv.y) * it2.y;
                float2 ac = *reinterpret_cast<const float2*>(g_Acc + ix);
                ac.x += DT3 * k0; ac.y += DT3 * k1;
                *reinterpret_cast<float2*>(g_Acc + ix) = ac;
                float2 hh = __half22float2(*reinterpret_cast<const __half2*>(g_Hh + ix));
                float2 hl = __half22float2(*reinterpret_cast<const __half2*>(g_Hl + ix));
                float h0 = hh.x + hl.x, h1 = hh.y + hl.y;
                const float w = (MODE == 1) ? HDT : DT;
                __half2 sn;
                sn.x = __float2half(h0 + w * k0);
                sn.y = __float2half(h1 + w * k1);
                __half2* dst = reinterpret_cast<__half2*>(((MODE == 1) ? g_A2 : g_A3) + ix);
                *dst = sn;
              } else {  // MODE == 3
                float2 sv = __half22float2(*reinterpret_cast<const __half2*>(g_A3 + ix));
                float k0 = (t0 - sv.x) * it2.x;
                float k1 = (t1 - sv.y) * it2.y;
                float2 ac = *reinterpret_cast<const float2*>(g_Acc + ix);
                float v0 = ac.x + DT6 * k0;
                float v1 = ac.y + DT6 * k1;
                __half hi0 = __float2half(v0);
                __half hi1 = __float2half(v1);
                __half2 oh; oh.x = hi0; oh.y = hi1;
                __half2 ol;
                ol.x = __float2half(v0 - __half2float(hi0));
                ol.y = __float2half(v1 - __half2float(hi1));
                *reinterpret_cast<__half2*>(g_Hh + ix) = oh;
                *reinterpret_cast<__half2*>(g_Hl + ix) = ol;
              }
            }
          }
        }
      }
    }
  }
}

// ---------------- launcher ----------------
extern "C" void kernel_launch(void* const* d_in, const int* in_sizes, int n_in,
                              void* d_out, int out_size) {
  (void)in_sizes; (void)n_in; (void)out_size;
  const float* x    = (const float*)d_in[0];
  const float* Wx   = (const float*)d_in[1];
  const float* bx   = (const float*)d_in[2];
  const float* W    = (const float*)d_in[3];
  const float* U    = (const float*)d_in[4];
  const float* bvec = (const float*)d_in[5];
  const float* tau  = (const float*)d_in[6];
  const float* Wf   = (const float*)d_in[7];
  const float* bf   = (const float*)d_in[8];
  float* out = (float*)d_out;

  cudaFuncSetAttribute(k_gemm<0>, cudaFuncAttributeMaxDynamicSharedMemorySize, ST_SMEM);
  cudaFuncSetAttribute(k_gemm<1>, cudaFuncAttributeMaxDynamicSharedMemorySize, ST_SMEM);
  cudaFuncSetAttribute(k_gemm<2>, cudaFuncAttributeMaxDynamicSharedMemorySize, ST_SMEM);
  cudaFuncSetAttribute(k_gemm<3>, cudaFuncAttributeMaxDynamicSharedMemorySize, ST_SMEM);
  cudaFuncSetAttribute(k_gemm<4>, cudaFuncAttributeMaxDynamicSharedMemorySize, ST_SMEM);
  cudaFuncSetAttribute(k_head,  cudaFuncAttributeMaxDynamicSharedMemorySize, 65536);
  cudaFuncSetAttribute(k_in,    cudaFuncAttributeMaxDynamicSharedMemorySize, 32768);

  k_prep<<<(HID * HID + HID * 1024) / 256, 256>>>(W, U, tau);
  k_in<<<BATCH / 32, 256, 32768>>>(x, Wx, bx);
  k_gemm<4><<<BATCH / 128, NTHR, ST_SMEM>>>(bvec);       // drive (hi/lo, K'=1024)
  for (int step = 0; step < NSTEPS; ++step) {
    k_gemm<0><<<BATCH / 128, NTHR, ST_SMEM>>>(nullptr);
    k_gemm<1><<<BATCH / 128, NTHR, ST_SMEM>>>(nullptr);
    k_gemm<2><<<BATCH / 128, NTHR, ST_SMEM>>>(nullptr);
    k_gemm<3><<<BATCH / 128, NTHR, ST_SMEM>>>(nullptr);
  }
  k_head<<<BATCH / 32, 256, 65536>>>(Wf, bf, out);
}